// round 8
// baseline (speedup 1.0000x reference)
#include <cuda_runtime.h>

#define N_USERS 50000
#define N_ITEMS 75000
#define N_NODES 125000
#define NNZ     1250000
#define EMB     64
#define N_LAYERS 3
#define BATCH   4096
#define SCAN_BLOCKS 489        // ceil(125000/256)

// Scratch (device globals — allocation-free per harness rules)
__device__ __align__(128) float g_fA  [N_NODES * EMB];                 // 32 MB
__device__ __align__(128) float g_fB  [N_NODES * EMB];                 // 32 MB
__device__ __align__(128) float g_agg [N_NODES * EMB];                 // 32 MB
__device__ __align__(128) float g_norm[N_LAYERS * N_NODES * EMB];      // 96 MB
// CSR scratch.  INVARIANT: g_cnt is all-zero at kernel_launch entry
// (zero-initialized at load; re-zeroed by gather_kernel every execution).
__device__ __align__(128) int   g_cnt   [N_NODES];
__device__ __align__(128) int   g_rowptr[N_NODES + 1];
__device__ __align__(128) int   g_cursor[N_NODES];
__device__ __align__(128) int   g_bsum  [512];
__device__ __align__(128) int   g_boff  [512];
__device__ __align__(128) int   g_cols  [NNZ];
__device__ __align__(128) float g_vals  [NNZ];

__device__ __forceinline__ float lrelu(float x) {
    return x > 0.0f ? x : 0.2f * x;
}

// Packed fp32x2 FMA (sm_103a FFMA2)
#define FMA2(acc, a, b) \
    asm("fma.rn.f32x2 %0, %1, %2, %0;" : "+l"(acc) : "l"(a), "l"(b))
#define PACK2(d, s) \
    asm("mov.b64 %0, {%1, %1};" : "=l"(d) : "f"(s))

__device__ __forceinline__ float lo2(unsigned long long v) {
    return __uint_as_float((unsigned)v);
}
__device__ __forceinline__ float hi2(unsigned long long v) {
    return __uint_as_float((unsigned)(v >> 32));
}

// ---------------------------------------------------------------------------
// histogram rows (g_cnt zero on entry, see invariant)
__global__ __launch_bounds__(256) void hist_kernel(const int* __restrict__ row) {
    int e = blockIdx.x * 256 + threadIdx.x;
    if (e < NNZ) atomicAdd(&g_cnt[row[e]], 1);
}

// ---------------------------------------------------------------------------
// per-block exclusive scan of g_cnt (shfl); exclusive -> g_rowptr, totals -> g_bsum
__global__ __launch_bounds__(256) void scan1_kernel() {
    __shared__ int wt[8];
    int tid  = threadIdx.x;
    int lane = tid & 31;
    int w    = tid >> 5;
    int i    = blockIdx.x * 256 + tid;
    int x    = (i < N_NODES) ? g_cnt[i] : 0;
    int v = x;                                     // inclusive within warp
    #pragma unroll
    for (int off = 1; off < 32; off <<= 1) {
        int n = __shfl_up_sync(0xffffffffu, v, off);
        if (lane >= off) v += n;
    }
    if (lane == 31) wt[w] = v;
    __syncthreads();
    if (w == 0 && lane < 8) {
        int s = wt[lane];
        #pragma unroll
        for (int off = 1; off < 8; off <<= 1) {
            int n = __shfl_up_sync(0x000000ffu, s, off);
            if (lane >= off) s += n;
        }
        wt[lane] = s;                              // inclusive warp totals
    }
    __syncthreads();
    int add = (w > 0) ? wt[w - 1] : 0;
    if (i < N_NODES) g_rowptr[i] = v - x + add;    // exclusive within block
    if (tid == 255) g_bsum[blockIdx.x] = v + add;  // block total
}

// single block: exclusive scan of 489 block sums (shfl-based)
__global__ __launch_bounds__(512) void scan2_kernel() {
    __shared__ int wt[16];
    int tid  = threadIdx.x;
    int lane = tid & 31;
    int w    = tid >> 5;
    int x = (tid < SCAN_BLOCKS) ? g_bsum[tid] : 0;
    int v = x;
    #pragma unroll
    for (int off = 1; off < 32; off <<= 1) {
        int n = __shfl_up_sync(0xffffffffu, v, off);
        if (lane >= off) v += n;
    }
    if (lane == 31) wt[w] = v;
    __syncthreads();
    if (w == 0 && lane < 16) {
        int s = wt[lane];
        #pragma unroll
        for (int off = 1; off < 16; off <<= 1) {
            int n = __shfl_up_sync(0x0000ffffu, s, off);
            if (lane >= off) s += n;
        }
        wt[lane] = s;
    }
    __syncthreads();
    int add = (w > 0) ? wt[w - 1] : 0;
    g_boff[tid] = v - x + add;
}

// apply block offsets; init cursor; set sentinel
__global__ __launch_bounds__(256) void scan3_kernel() {
    int i = blockIdx.x * 256 + threadIdx.x;
    if (i < N_NODES) {
        int v = g_rowptr[i] + g_boff[blockIdx.x];
        g_rowptr[i] = v;
        g_cursor[i] = v;
    }
    if (i == 0) g_rowptr[N_NODES] = NNZ;
}

// scatter edges into row-sorted order
__global__ __launch_bounds__(256) void scatter_kernel(const int*   __restrict__ row,
                                                      const int*   __restrict__ col,
                                                      const float* __restrict__ vals) {
    int e = blockIdx.x * 256 + threadIdx.x;
    if (e >= NNZ) return;
    int pos = atomicAdd(&g_cursor[row[e]], 1);
    g_cols[pos] = col[e];
    g_vals[pos] = vals[e];
}

// ---------------------------------------------------------------------------
// Gather-SpMM over CSR: agg[r] = sum_j val[j] * feat_in[col[j]]   (R4 core)
__global__ __launch_bounds__(256) void spmm_csr_kernel(const float* __restrict__ feat_in) {
    int t   = blockIdx.x * 256 + threadIdx.x;
    int r   = t >> 4;
    int seg = t & 15;
    if (r >= N_NODES) return;
    int j  = g_rowptr[r];
    int s1 = g_rowptr[r + 1];
    float4 acc = make_float4(0.f, 0.f, 0.f, 0.f);
    const float4* feat4 = (const float4*)feat_in;
    for (; j + 1 < s1; j += 2) {
        int   c0 = __ldg(g_cols + j);
        float v0 = __ldg(g_vals + j);
        int   c1 = __ldg(g_cols + j + 1);
        float v1 = __ldg(g_vals + j + 1);
        float4 f0 = __ldg(feat4 + c0 * 16 + seg);
        float4 f1 = __ldg(feat4 + c1 * 16 + seg);
        acc.x += v0 * f0.x + v1 * f1.x;
        acc.y += v0 * f0.y + v1 * f1.y;
        acc.z += v0 * f0.z + v1 * f1.z;
        acc.w += v0 * f0.w + v1 * f1.w;
    }
    if (j < s1) {
        int   c0 = __ldg(g_cols + j);
        float v0 = __ldg(g_vals + j);
        float4 f0 = __ldg(feat4 + c0 * 16 + seg);
        acc.x += v0 * f0.x;
        acc.y += v0 * f0.y;
        acc.z += v0 * f0.z;
        acc.w += v0 * f0.w;
    }
    ((float4*)g_agg)[r * 16 + seg] = acc;
}

// ---------------------------------------------------------------------------
// Dense per-node update (R4 core, measured 60us/launch), with feat_in/feat_out
// ping-pong instead of in-place g_feat.
#define M_TILE      128
#define PAIR_STRIDE 130
#define W_STRIDE    68
#define SA_FLOATS   (64 * PAIR_STRIDE)
#define SW_FLOATS   (64 * W_STRIDE)
#define DENSE_SMEM  ((2 * SA_FLOATS + 2 * SW_FLOATS) * 4)   // 101376 B

__global__ __launch_bounds__(256, 2) void dense_kernel(const float* __restrict__ feat_in,
                                                       float*       __restrict__ feat_out,
                                                       const float* __restrict__ W1,
                                                       const float* __restrict__ b1,
                                                       const float* __restrict__ W2,
                                                       const float* __restrict__ b2,
                                                       int layer) {
    extern __shared__ float smem[];
    float* sA  = smem;
    float* sAF = sA  + SA_FLOATS;
    float* sW1 = sAF + SA_FLOATS;
    float* sW2 = sW1 + SW_FLOATS;

    const int t    = threadIdx.x;
    const int tx   = t & 15;
    const int ty   = t >> 4;
    const int j0   = tx * 4;
    const int base = blockIdx.x * M_TILE;

    const float* W1l = W1 + layer * 4096;
    const float* W2l = W2 + layer * 4096;
    #pragma unroll
    for (int i = t; i < 4096; i += 256) {
        int j = i >> 6, k = i & 63;
        sW1[k * W_STRIDE + j] = W1l[i];
        sW2[k * W_STRIDE + j] = W2l[i];
    }

    #pragma unroll
    for (int idx = t; idx < M_TILE * 16; idx += 256) {
        int mm   = idx >> 4;
        int seg  = idx & 15;
        int node = base + mm;
        float4 a4 = make_float4(0.f, 0.f, 0.f, 0.f);
        float4 f4 = make_float4(0.f, 0.f, 0.f, 0.f);
        if (node < N_NODES) {
            a4 = ((const float4*)g_agg  )[node * 16 + seg];
            f4 = ((const float4*)feat_in)[node * 16 + seg];
        }
        int pbase = (mm >> 1) * PAIR_STRIDE + (mm & 1);
        #pragma unroll
        for (int i = 0; i < 4; ++i) {
            float av = (&a4.x)[i];
            float fv = (&f4.x)[i];
            int off = pbase + (seg * 4 + i) * 2;
            sA [off] = av;
            sAF[off] = av * fv;
        }
    }
    __syncthreads();

    unsigned long long acc1[16], acc2[16];
    #pragma unroll
    for (int i = 0; i < 16; ++i) { acc1[i] = 0ull; acc2[i] = 0ull; }

    const int p0 = ty * 4;

    #pragma unroll 8
    for (int k = 0; k < 64; ++k) {
        unsigned long long A2[4], AF2[4];
        #pragma unroll
        for (int mp = 0; mp < 4; ++mp) {
            A2 [mp] = *(const unsigned long long*)(sA  + (p0 + mp) * PAIR_STRIDE + 2 * k);
            AF2[mp] = *(const unsigned long long*)(sAF + (p0 + mp) * PAIR_STRIDE + 2 * k);
        }
        float4 w1 = *(const float4*)(sW1 + k * W_STRIDE + j0);
        float4 w2 = *(const float4*)(sW2 + k * W_STRIDE + j0);
        #pragma unroll
        for (int j = 0; j < 4; ++j) {
            unsigned long long wd1, wd2;
            PACK2(wd1, (&w1.x)[j]);
            PACK2(wd2, (&w2.x)[j]);
            #pragma unroll
            for (int mp = 0; mp < 4; ++mp) {
                FMA2(acc1[j * 4 + mp], A2[mp],  wd1);
                FMA2(acc2[j * 4 + mp], AF2[mp], wd2);
            }
        }
    }

    float bb1[4], bb2[4];
    #pragma unroll
    for (int j = 0; j < 4; ++j) {
        bb1[j] = __ldg(b1 + layer * 64 + j0 + j);
        bb2[j] = __ldg(b2 + layer * 64 + j0 + j);
    }
    float* normL = g_norm + (size_t)layer * N_NODES * EMB;

    #pragma unroll
    for (int mp = 0; mp < 4; ++mp) {
        #pragma unroll
        for (int h = 0; h < 2; ++h) {
            float o[4];
            #pragma unroll
            for (int j = 0; j < 4; ++j) {
                unsigned long long v1 = acc1[j * 4 + mp];
                unsigned long long v2 = acc2[j * 4 + mp];
                float a1 = (h ? hi2(v1) : lo2(v1)) + bb1[j];
                float a2 = (h ? hi2(v2) : lo2(v2)) + bb2[j];
                o[j] = lrelu(a1) + lrelu(a2);
            }
            float ss = o[0]*o[0] + o[1]*o[1] + o[2]*o[2] + o[3]*o[3];
            #pragma unroll
            for (int off = 8; off; off >>= 1)
                ss += __shfl_xor_sync(0xffffffffu, ss, off);
            float inv = __fdividef(1.0f, fmaxf(sqrtf(ss), 1e-12f));

            int node = base + ty * 8 + mp * 2 + h;
            if (node < N_NODES) {
                float4 ov = make_float4(o[0], o[1], o[2], o[3]);
                ((float4*)feat_out)[node * 16 + tx] = ov;
                float4 on = make_float4(o[0]*inv, o[1]*inv, o[2]*inv, o[3]*inv);
                ((float4*)normL)[node * 16 + tx] = on;
            }
        }
    }
}

// ---------------------------------------------------------------------------
// Final gather; also re-zeroes g_cnt to maintain the entry invariant.
__global__ __launch_bounds__(256) void gather_kernel(const int* __restrict__ user,
                                                     const int* __restrict__ pos,
                                                     const int* __restrict__ neg,
                                                     const float* __restrict__ emb,
                                                     float* __restrict__ out) {
    int o4 = blockIdx.x * 256 + threadIdx.x;
    if (o4 < N_NODES) g_cnt[o4] = 0;               // restore invariant
    if (o4 >= 3 * BATCH * 64) return;
    int c4 = o4 & 63;
    int rr = o4 >> 6;
    int tsel = rr / BATCH;
    int r    = rr - tsel * BATCH;
    int node = (tsel == 0) ? user[r]
             : (tsel == 1) ? (N_USERS + pos[r])
                           : (N_USERS + neg[r]);
    int part = c4 >> 4;
    int cc   = c4 & 15;
    float4 v;
    if (part == 0)
        v = ((const float4*)emb)[node * 16 + cc];
    else
        v = ((const float4*)(g_norm + (size_t)(part - 1) * N_NODES * EMB))[node * 16 + cc];
    ((float4*)out)[o4] = v;
}

// ---------------------------------------------------------------------------
extern "C" void kernel_launch(void* const* d_in, const int* in_sizes, int n_in,
                              void* d_out, int out_size) {
    const int*   user = (const int*)  d_in[0];
    const int*   pos  = (const int*)  d_in[1];
    const int*   neg  = (const int*)  d_in[2];
    const int*   row  = (const int*)  d_in[3];
    const int*   col  = (const int*)  d_in[4];
    const float* vals = (const float*)d_in[5];
    const float* emb  = (const float*)d_in[6];
    const float* W1   = (const float*)d_in[7];
    const float* b1   = (const float*)d_in[8];
    const float* W2   = (const float*)d_in[9];
    const float* b2   = (const float*)d_in[10];
    float* out = (float*)d_out;

    static bool attr_set = false;
    if (!attr_set) {
        cudaFuncSetAttribute(dense_kernel,
                             cudaFuncAttributeMaxDynamicSharedMemorySize, DENSE_SMEM);
        attr_set = true;
    }

    const int EDGE_BLOCKS  = (NNZ + 255) / 256;                 // 4883
    const int ROW16_BLOCKS = (N_NODES * 16 + 255) / 256;        // 7813
    const int DENSE_BLOCKS = (N_NODES + M_TILE - 1) / M_TILE;   // 977

    hist_kernel<<<EDGE_BLOCKS, 256>>>(row);
    scan1_kernel<<<SCAN_BLOCKS, 256>>>();
    scan2_kernel<<<1, 512>>>();
    scan3_kernel<<<SCAN_BLOCKS, 256>>>();
    scatter_kernel<<<EDGE_BLOCKS, 256>>>(row, col, vals);

    // ping-pong: emb -> fA -> fB -> fA
    const float* fin[3] = { emb,  g_fA, g_fB };
    float*       fout[3] = { g_fA, g_fB, g_fA };
    for (int l = 0; l < N_LAYERS; ++l) {
        spmm_csr_kernel<<<ROW16_BLOCKS, 256>>>(fin[l]);
        dense_kernel<<<DENSE_BLOCKS, 256, DENSE_SMEM>>>(fin[l], fout[l],
                                                        W1, b1, W2, b2, l);
    }
    gather_kernel<<<(3 * BATCH * 64 + 255) / 256, 256>>>(user, pos, neg, emb, out);
}

// round 9
// speedup vs baseline: 12.3174x; 12.3174x over previous
#include <cuda_runtime.h>

#define N_USERS 50000
#define N_ITEMS 75000
#define N_NODES 125000
#define NNZ     1250000
#define EMB     64
#define N_LAYERS 3
#define BATCH   4096
#define SCAN_BLOCKS 489        // ceil(125000/256)

// Scratch (device globals — allocation-free per harness rules)
__device__ __align__(128) float g_fA  [N_NODES * EMB];                 // 32 MB
__device__ __align__(128) float g_fB  [N_NODES * EMB];                 // 32 MB
__device__ __align__(128) float g_agg [N_NODES * EMB];                 // 32 MB
__device__ __align__(128) float g_norm[N_LAYERS * N_NODES * EMB];      // 96 MB
// CSR scratch.  INVARIANT: g_cnt is all-zero at kernel_launch entry
// (zero-initialized at load; re-zeroed by gather_kernel every execution).
__device__ __align__(128) int   g_cnt   [N_NODES];
__device__ __align__(128) int   g_rowptr[N_NODES + 1];
__device__ __align__(128) int   g_cursor[N_NODES];
__device__ __align__(128) int   g_bsum  [512];
__device__ __align__(128) int   g_boff  [512];
__device__ __align__(128) int   g_cols  [NNZ];
__device__ __align__(128) float g_vals  [NNZ];

__device__ __forceinline__ float lrelu(float x) {
    return x > 0.0f ? x : 0.2f * x;
}

// Packed fp32x2 FMA (sm_103a FFMA2)
#define FMA2(acc, a, b) \
    asm("fma.rn.f32x2 %0, %1, %2, %0;" : "+l"(acc) : "l"(a), "l"(b))
#define PACK2(d, s) \
    asm("mov.b64 %0, {%1, %1};" : "=l"(d) : "f"(s))

__device__ __forceinline__ float lo2(unsigned long long v) {
    return __uint_as_float((unsigned)v);
}
__device__ __forceinline__ float hi2(unsigned long long v) {
    return __uint_as_float((unsigned)(v >> 32));
}

// Device-side buffer selection (NEVER pass __device__ symbols from host!)
__device__ __forceinline__ const float* feat_in_for(const float* emb, int layer) {
    return (layer == 0) ? emb : (layer == 1 ? g_fA : g_fB);
}
__device__ __forceinline__ float* feat_out_for(int layer) {
    return (layer & 1) ? g_fB : g_fA;
}

// ---------------------------------------------------------------------------
// histogram rows (g_cnt zero on entry, see invariant)
__global__ __launch_bounds__(256) void hist_kernel(const int* __restrict__ row) {
    int e = blockIdx.x * 256 + threadIdx.x;
    if (e < NNZ) atomicAdd(&g_cnt[row[e]], 1);
}

// ---------------------------------------------------------------------------
// per-block exclusive scan of g_cnt (shfl); exclusive -> g_rowptr, totals -> g_bsum
__global__ __launch_bounds__(256) void scan1_kernel() {
    __shared__ int wt[8];
    int tid  = threadIdx.x;
    int lane = tid & 31;
    int w    = tid >> 5;
    int i    = blockIdx.x * 256 + tid;
    int x    = (i < N_NODES) ? g_cnt[i] : 0;
    int v = x;                                     // inclusive within warp
    #pragma unroll
    for (int off = 1; off < 32; off <<= 1) {
        int n = __shfl_up_sync(0xffffffffu, v, off);
        if (lane >= off) v += n;
    }
    if (lane == 31) wt[w] = v;
    __syncthreads();
    if (w == 0 && lane < 8) {
        int s = wt[lane];
        #pragma unroll
        for (int off = 1; off < 8; off <<= 1) {
            int n = __shfl_up_sync(0x000000ffu, s, off);
            if (lane >= off) s += n;
        }
        wt[lane] = s;                              // inclusive warp totals
    }
    __syncthreads();
    int add = (w > 0) ? wt[w - 1] : 0;
    if (i < N_NODES) g_rowptr[i] = v - x + add;    // exclusive within block
    if (tid == 255) g_bsum[blockIdx.x] = v + add;  // block total
}

// single block: exclusive scan of 489 block sums (shfl-based)
__global__ __launch_bounds__(512) void scan2_kernel() {
    __shared__ int wt[16];
    int tid  = threadIdx.x;
    int lane = tid & 31;
    int w    = tid >> 5;
    int x = (tid < SCAN_BLOCKS) ? g_bsum[tid] : 0;
    int v = x;
    #pragma unroll
    for (int off = 1; off < 32; off <<= 1) {
        int n = __shfl_up_sync(0xffffffffu, v, off);
        if (lane >= off) v += n;
    }
    if (lane == 31) wt[w] = v;
    __syncthreads();
    if (w == 0 && lane < 16) {
        int s = wt[lane];
        #pragma unroll
        for (int off = 1; off < 16; off <<= 1) {
            int n = __shfl_up_sync(0x0000ffffu, s, off);
            if (lane >= off) s += n;
        }
        wt[lane] = s;
    }
    __syncthreads();
    int add = (w > 0) ? wt[w - 1] : 0;
    g_boff[tid] = v - x + add;
}

// apply block offsets; init cursor; set sentinel
__global__ __launch_bounds__(256) void scan3_kernel() {
    int i = blockIdx.x * 256 + threadIdx.x;
    if (i < N_NODES) {
        int v = g_rowptr[i] + g_boff[blockIdx.x];
        g_rowptr[i] = v;
        g_cursor[i] = v;
    }
    if (i == 0) g_rowptr[N_NODES] = NNZ;
}

// scatter edges into row-sorted order
__global__ __launch_bounds__(256) void scatter_kernel(const int*   __restrict__ row,
                                                      const int*   __restrict__ col,
                                                      const float* __restrict__ vals) {
    int e = blockIdx.x * 256 + threadIdx.x;
    if (e >= NNZ) return;
    int pos = atomicAdd(&g_cursor[row[e]], 1);
    g_cols[pos] = col[e];
    g_vals[pos] = vals[e];
}

// ---------------------------------------------------------------------------
// Gather-SpMM over CSR: agg[r] = sum_j val[j] * feat_in[col[j]]   (R4 core)
__global__ __launch_bounds__(256) void spmm_csr_kernel(const float* __restrict__ emb,
                                                       int layer) {
    int t   = blockIdx.x * 256 + threadIdx.x;
    int r   = t >> 4;
    int seg = t & 15;
    if (r >= N_NODES) return;
    const float4* feat4 = (const float4*)feat_in_for(emb, layer);
    int j  = g_rowptr[r];
    int s1 = g_rowptr[r + 1];
    float4 acc = make_float4(0.f, 0.f, 0.f, 0.f);
    for (; j + 1 < s1; j += 2) {
        int   c0 = __ldg(g_cols + j);
        float v0 = __ldg(g_vals + j);
        int   c1 = __ldg(g_cols + j + 1);
        float v1 = __ldg(g_vals + j + 1);
        float4 f0 = __ldg(feat4 + c0 * 16 + seg);
        float4 f1 = __ldg(feat4 + c1 * 16 + seg);
        acc.x += v0 * f0.x + v1 * f1.x;
        acc.y += v0 * f0.y + v1 * f1.y;
        acc.z += v0 * f0.z + v1 * f1.z;
        acc.w += v0 * f0.w + v1 * f1.w;
    }
    if (j < s1) {
        int   c0 = __ldg(g_cols + j);
        float v0 = __ldg(g_vals + j);
        float4 f0 = __ldg(feat4 + c0 * 16 + seg);
        acc.x += v0 * f0.x;
        acc.y += v0 * f0.y;
        acc.z += v0 * f0.z;
        acc.w += v0 * f0.w;
    }
    ((float4*)g_agg)[r * 16 + seg] = acc;
}

// ---------------------------------------------------------------------------
// Dense per-node update (R4 core, measured 60us/launch); ping-pong buffers
// selected in device code via layer index.
#define M_TILE      128
#define PAIR_STRIDE 130
#define W_STRIDE    68
#define SA_FLOATS   (64 * PAIR_STRIDE)
#define SW_FLOATS   (64 * W_STRIDE)
#define DENSE_SMEM  ((2 * SA_FLOATS + 2 * SW_FLOATS) * 4)   // 101376 B

__global__ __launch_bounds__(256, 2) void dense_kernel(const float* __restrict__ emb,
                                                       const float* __restrict__ W1,
                                                       const float* __restrict__ b1,
                                                       const float* __restrict__ W2,
                                                       const float* __restrict__ b2,
                                                       int layer) {
    extern __shared__ float smem[];
    float* sA  = smem;
    float* sAF = sA  + SA_FLOATS;
    float* sW1 = sAF + SA_FLOATS;
    float* sW2 = sW1 + SW_FLOATS;

    const float* feat_in  = feat_in_for(emb, layer);
    float*       feat_out = feat_out_for(layer);

    const int t    = threadIdx.x;
    const int tx   = t & 15;
    const int ty   = t >> 4;
    const int j0   = tx * 4;
    const int base = blockIdx.x * M_TILE;

    const float* W1l = W1 + layer * 4096;
    const float* W2l = W2 + layer * 4096;
    #pragma unroll
    for (int i = t; i < 4096; i += 256) {
        int j = i >> 6, k = i & 63;
        sW1[k * W_STRIDE + j] = W1l[i];
        sW2[k * W_STRIDE + j] = W2l[i];
    }

    #pragma unroll
    for (int idx = t; idx < M_TILE * 16; idx += 256) {
        int mm   = idx >> 4;
        int seg  = idx & 15;
        int node = base + mm;
        float4 a4 = make_float4(0.f, 0.f, 0.f, 0.f);
        float4 f4 = make_float4(0.f, 0.f, 0.f, 0.f);
        if (node < N_NODES) {
            a4 = ((const float4*)g_agg  )[node * 16 + seg];
            f4 = ((const float4*)feat_in)[node * 16 + seg];
        }
        int pbase = (mm >> 1) * PAIR_STRIDE + (mm & 1);
        #pragma unroll
        for (int i = 0; i < 4; ++i) {
            float av = (&a4.x)[i];
            float fv = (&f4.x)[i];
            int off = pbase + (seg * 4 + i) * 2;
            sA [off] = av;
            sAF[off] = av * fv;
        }
    }
    __syncthreads();

    unsigned long long acc1[16], acc2[16];
    #pragma unroll
    for (int i = 0; i < 16; ++i) { acc1[i] = 0ull; acc2[i] = 0ull; }

    const int p0 = ty * 4;

    #pragma unroll 8
    for (int k = 0; k < 64; ++k) {
        unsigned long long A2[4], AF2[4];
        #pragma unroll
        for (int mp = 0; mp < 4; ++mp) {
            A2 [mp] = *(const unsigned long long*)(sA  + (p0 + mp) * PAIR_STRIDE + 2 * k);
            AF2[mp] = *(const unsigned long long*)(sAF + (p0 + mp) * PAIR_STRIDE + 2 * k);
        }
        float4 w1 = *(const float4*)(sW1 + k * W_STRIDE + j0);
        float4 w2 = *(const float4*)(sW2 + k * W_STRIDE + j0);
        #pragma unroll
        for (int j = 0; j < 4; ++j) {
            unsigned long long wd1, wd2;
            PACK2(wd1, (&w1.x)[j]);
            PACK2(wd2, (&w2.x)[j]);
            #pragma unroll
            for (int mp = 0; mp < 4; ++mp) {
                FMA2(acc1[j * 4 + mp], A2[mp],  wd1);
                FMA2(acc2[j * 4 + mp], AF2[mp], wd2);
            }
        }
    }

    float bb1[4], bb2[4];
    #pragma unroll
    for (int j = 0; j < 4; ++j) {
        bb1[j] = __ldg(b1 + layer * 64 + j0 + j);
        bb2[j] = __ldg(b2 + layer * 64 + j0 + j);
    }
    float* normL = g_norm + (size_t)layer * N_NODES * EMB;

    #pragma unroll
    for (int mp = 0; mp < 4; ++mp) {
        #pragma unroll
        for (int h = 0; h < 2; ++h) {
            float o[4];
            #pragma unroll
            for (int j = 0; j < 4; ++j) {
                unsigned long long v1 = acc1[j * 4 + mp];
                unsigned long long v2 = acc2[j * 4 + mp];
                float a1 = (h ? hi2(v1) : lo2(v1)) + bb1[j];
                float a2 = (h ? hi2(v2) : lo2(v2)) + bb2[j];
                o[j] = lrelu(a1) + lrelu(a2);
            }
            float ss = o[0]*o[0] + o[1]*o[1] + o[2]*o[2] + o[3]*o[3];
            #pragma unroll
            for (int off = 8; off; off >>= 1)
                ss += __shfl_xor_sync(0xffffffffu, ss, off);
            float inv = __fdividef(1.0f, fmaxf(sqrtf(ss), 1e-12f));

            int node = base + ty * 8 + mp * 2 + h;
            if (node < N_NODES) {
                float4 ov = make_float4(o[0], o[1], o[2], o[3]);
                ((float4*)feat_out)[node * 16 + tx] = ov;
                float4 on = make_float4(o[0]*inv, o[1]*inv, o[2]*inv, o[3]*inv);
                ((float4*)normL)[node * 16 + tx] = on;
            }
        }
    }
}

// ---------------------------------------------------------------------------
// Final gather; also re-zeroes g_cnt to maintain the entry invariant.
__global__ __launch_bounds__(256) void gather_kernel(const int* __restrict__ user,
                                                     const int* __restrict__ pos,
                                                     const int* __restrict__ neg,
                                                     const float* __restrict__ emb,
                                                     float* __restrict__ out) {
    int o4 = blockIdx.x * 256 + threadIdx.x;
    if (o4 < N_NODES) g_cnt[o4] = 0;               // restore invariant
    if (o4 >= 3 * BATCH * 64) return;
    int c4 = o4 & 63;
    int rr = o4 >> 6;
    int tsel = rr / BATCH;
    int r    = rr - tsel * BATCH;
    int node = (tsel == 0) ? user[r]
             : (tsel == 1) ? (N_USERS + pos[r])
                           : (N_USERS + neg[r]);
    int part = c4 >> 4;
    int cc   = c4 & 15;
    float4 v;
    if (part == 0)
        v = ((const float4*)emb)[node * 16 + cc];
    else
        v = ((const float4*)(g_norm + (size_t)(part - 1) * N_NODES * EMB))[node * 16 + cc];
    ((float4*)out)[o4] = v;
}

// ---------------------------------------------------------------------------
extern "C" void kernel_launch(void* const* d_in, const int* in_sizes, int n_in,
                              void* d_out, int out_size) {
    const int*   user = (const int*)  d_in[0];
    const int*   pos  = (const int*)  d_in[1];
    const int*   neg  = (const int*)  d_in[2];
    const int*   row  = (const int*)  d_in[3];
    const int*   col  = (const int*)  d_in[4];
    const float* vals = (const float*)d_in[5];
    const float* emb  = (const float*)d_in[6];
    const float* W1   = (const float*)d_in[7];
    const float* b1   = (const float*)d_in[8];
    const float* W2   = (const float*)d_in[9];
    const float* b2   = (const float*)d_in[10];
    float* out = (float*)d_out;

    static bool attr_set = false;
    if (!attr_set) {
        cudaFuncSetAttribute(dense_kernel,
                             cudaFuncAttributeMaxDynamicSharedMemorySize, DENSE_SMEM);
        attr_set = true;
    }

    const int EDGE_BLOCKS  = (NNZ + 255) / 256;                 // 4883
    const int ROW16_BLOCKS = (N_NODES * 16 + 255) / 256;        // 7813
    const int DENSE_BLOCKS = (N_NODES + M_TILE - 1) / M_TILE;   // 977

    hist_kernel<<<EDGE_BLOCKS, 256>>>(row);
    scan1_kernel<<<SCAN_BLOCKS, 256>>>();
    scan2_kernel<<<1, 512>>>();
    scan3_kernel<<<SCAN_BLOCKS, 256>>>();
    scatter_kernel<<<EDGE_BLOCKS, 256>>>(row, col, vals);

    for (int l = 0; l < N_LAYERS; ++l) {
        spmm_csr_kernel<<<ROW16_BLOCKS, 256>>>(emb, l);
        dense_kernel<<<DENSE_BLOCKS, 256, DENSE_SMEM>>>(emb, W1, b1, W2, b2, l);
    }
    gather_kernel<<<(3 * BATCH * 64 + 255) / 256, 256>>>(user, pos, neg, emb, out);
}

// round 11
// speedup vs baseline: 12.3265x; 1.0007x over previous
#include <cuda_runtime.h>
#include <cstdint>

#define N_USERS 50000
#define N_ITEMS 75000
#define N_NODES 125000
#define NNZ     1250000
#define EMB     64
#define N_LAYERS 3
#define BATCH   4096
#define SCAN_BLOCKS 489        // ceil(125000/256)

// Scratch (device globals — allocation-free per harness rules)
__device__ __align__(128) float g_fL0 [N_NODES * EMB];                 // 32 MB
__device__ __align__(128) float g_fL1 [N_NODES * EMB];                 // 32 MB
__device__ __align__(128) float g_fL2 [N_NODES * EMB];                 // 32 MB
__device__ __align__(128) float g_agg [N_NODES * EMB];                 // 32 MB
__device__ __align__(128) float g_inv [N_LAYERS * N_NODES];            // per-node 1/||o||
// CSR scratch.  INVARIANT: g_cnt and g_desc are all-zero at kernel_launch
// entry (zero-initialized at load; re-zeroed by gather_kernel every run).
__device__ __align__(128) int      g_cnt   [N_NODES];
__device__ __align__(128) int      g_rowptr[N_NODES + 1];
__device__ __align__(128) int      g_cursor[N_NODES];
__device__ __align__(128) unsigned g_desc  [512];        // lookback descriptors
__device__ __align__(128) int      g_cols  [NNZ];
__device__ __align__(128) float    g_vals  [NNZ];

#define FLAG_AGG 0x40000000u
#define FLAG_PRE 0x80000000u
#define VAL_MASK 0x3FFFFFFFu

__device__ __forceinline__ float lrelu(float x) {
    return x > 0.0f ? x : 0.2f * x;
}

// Packed fp32x2 FMA (sm_103a FFMA2)
#define FMA2(acc, a, b) \
    asm("fma.rn.f32x2 %0, %1, %2, %0;" : "+l"(acc) : "l"(a), "l"(b))
#define PACK2(d, s) \
    asm("mov.b64 %0, {%1, %1};" : "=l"(d) : "f"(s))

__device__ __forceinline__ float lo2(unsigned long long v) {
    return __uint_as_float((unsigned)v);
}
__device__ __forceinline__ float hi2(unsigned long long v) {
    return __uint_as_float((unsigned)(v >> 32));
}

// Device-side buffer selection (NEVER pass __device__ symbols from host!)
__device__ __forceinline__ const float* feat_in_for(const float* emb, int layer) {
    return (layer == 0) ? emb : (layer == 1 ? g_fL0 : g_fL1);
}
__device__ __forceinline__ float* feat_out_for(int layer) {
    return (layer == 0) ? g_fL0 : (layer == 1 ? g_fL1 : g_fL2);
}
__device__ __forceinline__ const float* feat_layer(int l) {
    return (l == 0) ? g_fL0 : (l == 1 ? g_fL1 : g_fL2);
}

// ---------------------------------------------------------------------------
// histogram rows (g_cnt zero on entry, see invariant)
__global__ __launch_bounds__(256) void hist_kernel(const int* __restrict__ row) {
    int e = blockIdx.x * 256 + threadIdx.x;
    if (e < NNZ) atomicAdd(&g_cnt[row[e]], 1);
}

// ---------------------------------------------------------------------------
// Single-pass exclusive scan of g_cnt with decoupled lookback.
// Writes g_rowptr, g_cursor, and the NNZ sentinel.  One launch.
__global__ __launch_bounds__(256) void scan_lookback_kernel() {
    __shared__ int wt[8];
    __shared__ int s_run;
    const int tid  = threadIdx.x;
    const int lane = tid & 31;
    const int w    = tid >> 5;
    const int b    = blockIdx.x;
    const int i    = b * 256 + tid;

    int x = (i < N_NODES) ? g_cnt[i] : 0;
    int v = x;                                     // inclusive within warp
    #pragma unroll
    for (int off = 1; off < 32; off <<= 1) {
        int n = __shfl_up_sync(0xffffffffu, v, off);
        if (lane >= off) v += n;
    }
    if (lane == 31) wt[w] = v;
    __syncthreads();
    if (w == 0 && lane < 8) {
        int s = wt[lane];
        #pragma unroll
        for (int off = 1; off < 8; off <<= 1) {
            int n = __shfl_up_sync(0x000000ffu, s, off);
            if (lane >= off) s += n;
        }
        wt[lane] = s;                              // inclusive warp totals
    }
    __syncthreads();
    const int add  = (w > 0) ? wt[w - 1] : 0;
    const int excl = v - x + add;                  // exclusive within block
    __syncthreads();                               // wt reads done
    const int agg  = wt[7];                        // block total

    // publish AGG, then lookback (thread 0)
    if (tid == 0) {
        if (b == 0) {
            atomicExch(&g_desc[0], FLAG_PRE | (unsigned)agg);
            s_run = 0;
        } else {
            atomicExch(&g_desc[b], FLAG_AGG | (unsigned)agg);
            int run = 0;
            int p = b - 1;
            while (true) {
                unsigned s;
                do { s = atomicAdd(&g_desc[p], 0u); } while (s == 0u);
                run += (int)(s & VAL_MASK);
                if (s & FLAG_PRE) break;
                --p;
            }
            atomicExch(&g_desc[b], FLAG_PRE | (unsigned)(run + agg));
            s_run = run;
        }
    }
    __syncthreads();
    const int off = s_run + excl;
    if (i < N_NODES) {
        g_rowptr[i] = off;
        g_cursor[i] = off;
    }
    if (i == N_NODES - 1) g_rowptr[N_NODES] = NNZ;
}

// scatter edges into row-sorted order
__global__ __launch_bounds__(256) void scatter_kernel(const int*   __restrict__ row,
                                                      const int*   __restrict__ col,
                                                      const float* __restrict__ vals) {
    int e = blockIdx.x * 256 + threadIdx.x;
    if (e >= NNZ) return;
    int pos = atomicAdd(&g_cursor[row[e]], 1);
    g_cols[pos] = col[e];
    g_vals[pos] = vals[e];
}

// ---------------------------------------------------------------------------
// Gather-SpMM over CSR (R4 core + 4-edge unroll for MLP)
__global__ __launch_bounds__(256) void spmm_csr_kernel(const float* __restrict__ emb,
                                                       int layer) {
    int t   = blockIdx.x * 256 + threadIdx.x;
    int r   = t >> 4;
    int seg = t & 15;
    if (r >= N_NODES) return;
    const float4* feat4 = (const float4*)feat_in_for(emb, layer);
    int j  = g_rowptr[r];
    int s1 = g_rowptr[r + 1];
    float4 acc = make_float4(0.f, 0.f, 0.f, 0.f);
    for (; j + 3 < s1; j += 4) {
        int   c0 = __ldg(g_cols + j);
        int   c1 = __ldg(g_cols + j + 1);
        int   c2 = __ldg(g_cols + j + 2);
        int   c3 = __ldg(g_cols + j + 3);
        float v0 = __ldg(g_vals + j);
        float v1 = __ldg(g_vals + j + 1);
        float v2 = __ldg(g_vals + j + 2);
        float v3 = __ldg(g_vals + j + 3);
        float4 f0 = __ldg(feat4 + c0 * 16 + seg);
        float4 f1 = __ldg(feat4 + c1 * 16 + seg);
        float4 f2 = __ldg(feat4 + c2 * 16 + seg);
        float4 f3 = __ldg(feat4 + c3 * 16 + seg);
        acc.x += v0 * f0.x + v1 * f1.x + v2 * f2.x + v3 * f3.x;
        acc.y += v0 * f0.y + v1 * f1.y + v2 * f2.y + v3 * f3.y;
        acc.z += v0 * f0.z + v1 * f1.z + v2 * f2.z + v3 * f3.z;
        acc.w += v0 * f0.w + v1 * f1.w + v2 * f2.w + v3 * f3.w;
    }
    for (; j < s1; ++j) {
        int   c0 = __ldg(g_cols + j);
        float v0 = __ldg(g_vals + j);
        float4 f0 = __ldg(feat4 + c0 * 16 + seg);
        acc.x += v0 * f0.x;
        acc.y += v0 * f0.y;
        acc.z += v0 * f0.z;
        acc.w += v0 * f0.w;
    }
    ((float4*)g_agg)[r * 16 + seg] = acc;
}

// ---------------------------------------------------------------------------
// Dense per-node update (R4 core, measured 60us/launch).  Epilogue stores
// feat_out + per-node inv scalar only (norm applied lazily in gather).
#define M_TILE      128
#define PAIR_STRIDE 130
#define W_STRIDE    68
#define SA_FLOATS   (64 * PAIR_STRIDE)
#define SW_FLOATS   (64 * W_STRIDE)
#define DENSE_SMEM  ((2 * SA_FLOATS + 2 * SW_FLOATS) * 4)   // 101376 B

__global__ __launch_bounds__(256, 2) void dense_kernel(const float* __restrict__ emb,
                                                       const float* __restrict__ W1,
                                                       const float* __restrict__ b1,
                                                       const float* __restrict__ W2,
                                                       const float* __restrict__ b2,
                                                       int layer) {
    extern __shared__ float smem[];
    float* sA  = smem;
    float* sAF = sA  + SA_FLOATS;
    float* sW1 = sAF + SA_FLOATS;
    float* sW2 = sW1 + SW_FLOATS;

    const float* feat_in  = feat_in_for(emb, layer);
    float*       feat_out = feat_out_for(layer);

    const int t    = threadIdx.x;
    const int tx   = t & 15;
    const int ty   = t >> 4;
    const int j0   = tx * 4;
    const int base = blockIdx.x * M_TILE;

    const float* W1l = W1 + layer * 4096;
    const float* W2l = W2 + layer * 4096;
    #pragma unroll
    for (int i = t; i < 4096; i += 256) {
        int j = i >> 6, k = i & 63;
        sW1[k * W_STRIDE + j] = W1l[i];
        sW2[k * W_STRIDE + j] = W2l[i];
    }

    #pragma unroll
    for (int idx = t; idx < M_TILE * 16; idx += 256) {
        int mm   = idx >> 4;
        int seg  = idx & 15;
        int node = base + mm;
        float4 a4 = make_float4(0.f, 0.f, 0.f, 0.f);
        float4 f4 = make_float4(0.f, 0.f, 0.f, 0.f);
        if (node < N_NODES) {
            a4 = ((const float4*)g_agg  )[node * 16 + seg];
            f4 = ((const float4*)feat_in)[node * 16 + seg];
        }
        int pbase = (mm >> 1) * PAIR_STRIDE + (mm & 1);
        #pragma unroll
        for (int i = 0; i < 4; ++i) {
            float av = (&a4.x)[i];
            float fv = (&f4.x)[i];
            int off = pbase + (seg * 4 + i) * 2;
            sA [off] = av;
            sAF[off] = av * fv;
        }
    }
    __syncthreads();

    unsigned long long acc1[16], acc2[16];
    #pragma unroll
    for (int i = 0; i < 16; ++i) { acc1[i] = 0ull; acc2[i] = 0ull; }

    const int p0 = ty * 4;

    #pragma unroll 8
    for (int k = 0; k < 64; ++k) {
        unsigned long long A2[4], AF2[4];
        #pragma unroll
        for (int mp = 0; mp < 4; ++mp) {
            A2 [mp] = *(const unsigned long long*)(sA  + (p0 + mp) * PAIR_STRIDE + 2 * k);
            AF2[mp] = *(const unsigned long long*)(sAF + (p0 + mp) * PAIR_STRIDE + 2 * k);
        }
        float4 w1 = *(const float4*)(sW1 + k * W_STRIDE + j0);
        float4 w2 = *(const float4*)(sW2 + k * W_STRIDE + j0);
        #pragma unroll
        for (int j = 0; j < 4; ++j) {
            unsigned long long wd1, wd2;
            PACK2(wd1, (&w1.x)[j]);
            PACK2(wd2, (&w2.x)[j]);
            #pragma unroll
            for (int mp = 0; mp < 4; ++mp) {
                FMA2(acc1[j * 4 + mp], A2[mp],  wd1);
                FMA2(acc2[j * 4 + mp], AF2[mp], wd2);
            }
        }
    }

    float bb1[4], bb2[4];
    #pragma unroll
    for (int j = 0; j < 4; ++j) {
        bb1[j] = __ldg(b1 + layer * 64 + j0 + j);
        bb2[j] = __ldg(b2 + layer * 64 + j0 + j);
    }
    float* invL = g_inv + layer * N_NODES;

    #pragma unroll
    for (int mp = 0; mp < 4; ++mp) {
        #pragma unroll
        for (int h = 0; h < 2; ++h) {
            float o[4];
            #pragma unroll
            for (int j = 0; j < 4; ++j) {
                unsigned long long v1 = acc1[j * 4 + mp];
                unsigned long long v2 = acc2[j * 4 + mp];
                float a1 = (h ? hi2(v1) : lo2(v1)) + bb1[j];
                float a2 = (h ? hi2(v2) : lo2(v2)) + bb2[j];
                o[j] = lrelu(a1) + lrelu(a2);
            }
            float ss = o[0]*o[0] + o[1]*o[1] + o[2]*o[2] + o[3]*o[3];
            #pragma unroll
            for (int off = 8; off; off >>= 1)
                ss += __shfl_xor_sync(0xffffffffu, ss, off);
            float inv = __fdividef(1.0f, fmaxf(sqrtf(ss), 1e-12f));

            int node = base + ty * 8 + mp * 2 + h;
            if (node < N_NODES) {
                float4 ov = make_float4(o[0], o[1], o[2], o[3]);
                ((float4*)feat_out)[node * 16 + tx] = ov;
                if (tx == 0) invL[node] = inv;
            }
        }
    }
}

// ---------------------------------------------------------------------------
// Final gather: out row = concat(emb, n0, n1, n2), nL = feat_L * inv_L.
// Also re-zeroes g_cnt and g_desc to maintain the entry invariant.
__global__ __launch_bounds__(256) void gather_kernel(const int* __restrict__ user,
                                                     const int* __restrict__ pos,
                                                     const int* __restrict__ neg,
                                                     const float* __restrict__ emb,
                                                     float* __restrict__ out) {
    int o4 = blockIdx.x * 256 + threadIdx.x;
    if (o4 < N_NODES) g_cnt[o4] = 0;               // restore invariant
    if (o4 < 512)     g_desc[o4] = 0u;             // restore invariant
    if (o4 >= 3 * BATCH * 64) return;
    int c4 = o4 & 63;
    int rr = o4 >> 6;
    int tsel = rr / BATCH;
    int r    = rr - tsel * BATCH;
    int node = (tsel == 0) ? user[r]
             : (tsel == 1) ? (N_USERS + pos[r])
                           : (N_USERS + neg[r]);
    int part = c4 >> 4;
    int cc   = c4 & 15;
    float4 v;
    if (part == 0) {
        v = ((const float4*)emb)[node * 16 + cc];
    } else {
        int l = part - 1;
        v = ((const float4*)feat_layer(l))[node * 16 + cc];
        float inv = g_inv[l * N_NODES + node];
        v.x *= inv; v.y *= inv; v.z *= inv; v.w *= inv;
    }
    ((float4*)out)[o4] = v;
}

// ---------------------------------------------------------------------------
extern "C" void kernel_launch(void* const* d_in, const int* in_sizes, int n_in,
                              void* d_out, int out_size) {
    const int*   user = (const int*)  d_in[0];
    const int*   pos  = (const int*)  d_in[1];
    const int*   neg  = (const int*)  d_in[2];
    const int*   row  = (const int*)  d_in[3];
    const int*   col  = (const int*)  d_in[4];
    const float* vals = (const float*)d_in[5];
    const float* emb  = (const float*)d_in[6];
    const float* W1   = (const float*)d_in[7];
    const float* b1   = (const float*)d_in[8];
    const float* W2   = (const float*)d_in[9];
    const float* b2   = (const float*)d_in[10];
    float* out = (float*)d_out;

    static bool attr_set = false;
    if (!attr_set) {
        cudaFuncSetAttribute(dense_kernel,
                             cudaFuncAttributeMaxDynamicSharedMemorySize, DENSE_SMEM);
        attr_set = true;
    }

    const int EDGE_BLOCKS  = (NNZ + 255) / 256;                 // 4883
    const int ROW16_BLOCKS = (N_NODES * 16 + 255) / 256;        // 7813
    const int DENSE_BLOCKS = (N_NODES + M_TILE - 1) / M_TILE;   // 977

    hist_kernel<<<EDGE_BLOCKS, 256>>>(row);
    scan_lookback_kernel<<<SCAN_BLOCKS, 256>>>();
    scatter_kernel<<<EDGE_BLOCKS, 256>>>(row, col, vals);

    for (int l = 0; l < N_LAYERS; ++l) {
        spmm_csr_kernel<<<ROW16_BLOCKS, 256>>>(emb, l);
        dense_kernel<<<DENSE_BLOCKS, 256, DENSE_SMEM>>>(emb, W1, b1, W2, b2, l);
    }
    gather_kernel<<<(3 * BATCH * 64 + 255) / 256, 256>>>(user, pos, neg, emb, out);
}